// round 10
// baseline (speedup 1.0000x reference)
#include <cuda_runtime.h>
#include <math.h>

#define BB 8
#define CC 4
#define HH 192
#define WW 192
#define HW (HH*WW)
#define NP 24          // (batch, class) pairs
#define NM 48          // (pair, direction)
#define SENT_KEY 73727 // key for f >= 1e9 (empty source surface)
#define SPLITS 3
#define RS 64          // rows per split

// dynamic smem layout (bytes)
#define OFF_G     0        // float [HW]   147456
#define OFF_LIST  147456   // u16 [12288]  24576  (aliased by hist/fine during selection)
#define OFF_FGP   172032   // u32 [1152]
#define OFF_FGG   176640   // u32 [1152]
#define OFF_SFP   181248   // u32 [1152]
#define OFF_SFG   185856   // u32 [1152]
#define OFF_ROWC  190464   // int [192]
#define OFF_ROWO  191232   // int [192]
#define OFF_MISC  192000   // int [8]
#define SMEM_TOTAL 192032

__device__ __align__(16) unsigned char d_pred[BB*HW];
__device__ int   d_keys[NM*HW];   // per-mask keys at deterministic offsets
__device__ int   d_tick[NM];      // per-mask split tickets
__device__ float d_res[NM*2];     // [m][0]=p95, [m][1]=p100
__device__ int   d_done;          // final-reduce ticket

extern __shared__ char smem[];

// ---------------------------------------------------------------- pre: argmax (softmax monotone; first-max ties)
// Also clears all tickets.
__global__ void argmax_kernel(const float* __restrict__ logits) {
    int idx = blockIdx.x*blockDim.x + threadIdx.x;
    if (idx < NM) d_tick[idx] = 0;
    if (idx == NM) d_done = 0;
    int pix4 = idx * 4;
    if (pix4 >= BB*HW) return;
    int b = pix4 / HW;
    int p = pix4 - b*HW;
    const float* base = logits + (size_t)b*CC*HW + p;
    float4 v0 = *(const float4*)(base);
    float4 v1 = *(const float4*)(base + HW);
    float4 v2 = *(const float4*)(base + 2*HW);
    float4 v3 = *(const float4*)(base + 3*HW);
    uchar4 r;
    #define AMAX(cp, dst) { \
        float bv = v0.cp; int bi = 0; \
        if (v1.cp > bv) { bv = v1.cp; bi = 1; } \
        if (v2.cp > bv) { bv = v2.cp; bi = 2; } \
        if (v3.cp > bv) { bv = v3.cp; bi = 3; } \
        dst = (unsigned char)bi; }
    AMAX(x, r.x) AMAX(y, r.y) AMAX(z, r.z) AMAX(w, r.w)
    #undef AMAX
    *(uchar4*)(d_pred + pix4) = r;
}

// ---------------------------------------------------------------- mega: one (mask, row-band) per block
__global__ void __launch_bounds__(1024) mega_kernel(const int* __restrict__ target,
                                                    float* __restrict__ out) {
    float*          gS   = (float*)(smem + OFF_G);
    unsigned short* list = (unsigned short*)(smem + OFF_LIST);
    unsigned* fgP = (unsigned*)(smem + OFF_FGP);
    unsigned* fgG = (unsigned*)(smem + OFF_FGG);
    unsigned* sfP = (unsigned*)(smem + OFF_SFP);
    unsigned* sfG = (unsigned*)(smem + OFF_SFG);
    int* rowc = (int*)(smem + OFF_ROWC);
    int* rowo = (int*)(smem + OFF_ROWO);
    int* misc = (int*)(smem + OFF_MISC);

    const int T = 1024;
    int m  = blockIdx.x;
    int sy = blockIdx.y;
    int r0 = sy*RS, r1 = r0 + RS;
    int pairI = m >> 1;
    int b = pairI / 3;
    int c = pairI - b*3 + 1;
    int tid = threadIdx.x;
    int lane = tid & 31;
    int wid = tid >> 5;

    // ---- A: fg bitmaps from pred bytes / int32 target (word-per-thread, no atomics)
    {
        unsigned crep = (unsigned)c * 0x01010101u;
        const uint4* pb = (const uint4*)(d_pred + b*HW);
        const int4*  tb = (const int4*)(target + (size_t)b*HW);
        for (int k = tid; k < 1152; k += T) {
            unsigned wp = 0;
            uint4 pa = pb[k*2], pc = pb[k*2 + 1];
            #define NIB(word, sh) { \
                unsigned nb = ((__vcmpeq4(word, crep) & 0x01010101u) * 0x01020408u) >> 24; \
                wp |= nb << (sh); }
            NIB(pa.x, 0) NIB(pa.y, 4) NIB(pa.z, 8) NIB(pa.w, 12)
            NIB(pc.x, 16) NIB(pc.y, 20) NIB(pc.z, 24) NIB(pc.w, 28)
            #undef NIB
            fgP[k] = wp;
            unsigned wg = 0;
            #pragma unroll
            for (int q = 0; q < 8; q++) {
                int4 tv = tb[k*8 + q];
                wg |= ((tv.x==c)?1u:0u) << (4*q);
                wg |= ((tv.y==c)?2u:0u) << (4*q);
                wg |= ((tv.z==c)?4u:0u) << (4*q);
                wg |= ((tv.w==c)?8u:0u) << (4*q);
            }
            fgG[k] = wg;
        }
    }
    if (tid == 0) { misc[1] = 0; }
    __syncthreads();

    // ---- B: 4-neighbor surfaces via bit ops (image border = background)
    for (int idx = tid; idx < 2304; idx += T) {
        const unsigned* fg = (idx < 1152) ? fgP : fgG;
        unsigned* sf = (idx < 1152) ? sfP : sfG;
        int k = (idx < 1152) ? idx : idx - 1152;
        int i = k / 6, w = k - (k/6)*6;
        unsigned f  = fg[k];
        unsigned up = (i > 0)    ? fg[k-6] : 0u;
        unsigned dn = (i < HH-1) ? fg[k+6] : 0u;
        unsigned lw = (w > 0) ? fg[k-1] : 0u;
        unsigned nx = (w < 5) ? fg[k+1] : 0u;
        unsigned lf = (f << 1) | (lw >> 31);
        unsigned rt = (f >> 1) | (nx << 31);
        sf[k] = f & ~(up & dn & lf & rt);
    }
    __syncthreads();

    const unsigned* sS = (m & 1) ? sfG : sfP;   // source surface (distance field of mask m)
    const unsigned* sO = (m & 1) ? sfP : sfG;   // opposite surface (sample points)

    // ---- C (threads 0-191): full-column EDT into float gS (1e9f = empty column)
    // ---- D1 (threads 192-383, concurrent): per-row popcounts of the sample surface
    if (tid < WW) {
        int j = tid; int ws = j >> 5; unsigned bm = 1u << (j & 31);
        int cnt = 255;
        for (int i = 0; i < HH; i++) {
            bool sv = (sS[i*6 + ws] & bm) != 0;
            cnt = sv ? 0 : min(cnt + 1, 255);
            gS[i*WW + j] = (float)cnt;
        }
        cnt = 255;
        for (int i = HH-1; i >= 0; i--) {
            int du = (int)gS[i*WW + j];
            cnt = (du == 0) ? 0 : min(cnt + 1, 255);
            int d = min(cnt, du);
            gS[i*WW + j] = (d >= HH) ? 1e9f : (float)(d*d);
        }
    } else if (tid < 2*WW) {
        int r = tid - WW;
        int s = 0;
        #pragma unroll
        for (int w = 0; w < 6; w++) s += __popc(sO[r*6 + w]);
        rowc[r] = s;
    }
    __syncthreads();

    // ---- D2: exclusive prefix over 192 row counts (warp 0) -> global key offsets
    if (tid < 32) {
        int loc[6]; int lsum = 0;
        #pragma unroll
        for (int k = 0; k < 6; k++) { loc[k] = lsum; lsum += rowc[tid*6 + k]; }
        int x = lsum;
        #pragma unroll
        for (int off = 1; off < 32; off <<= 1) {
            int y = __shfl_up_sync(0xffffffffu, x, off);
            if (lane >= off) x += y;
        }
        int excl = x - lsum;
        #pragma unroll
        for (int k = 0; k < 6; k++) rowo[tid*6 + k] = excl + loc[k];
        if (tid == 31) misc[0] = x;   // total sample count n (same in all splits)
    }
    __syncthreads();
    int n = misc[0];
    int base0 = rowo[r0];
    int hi = (r1 == HH) ? n : rowo[r1];
    int nloc = hi - base0;

    // ---- D3: scatter this band's (row,col) samples (no atomics)
    for (int r = r0 + wid; r < r1; r += 32) {
        int base = rowo[r] - base0;
        #pragma unroll
        for (int w = 0; w < 6; w++) {
            unsigned bits = sO[r*6 + w];
            if ((bits >> lane) & 1)
                list[base + __popc(bits & ((1u << lane) - 1u))] =
                    (unsigned short)((r << 8) | (w*32 + lane));
            base += __popc(bits);
        }
    }
    __syncthreads();

    // ---- E: exact outward-pruned min-plus; keys -> global at deterministic offsets
    int* gkeys = d_keys + m*HW;
    for (int s = tid; s < nloc; s += T) {
        int e = (int)list[s];
        int r = e >> 8, jj = e & 255;
        const float* grow = gS + r*WW;
        float v = grow[jj];
        for (int dd = 1; dd < WW; dd += 2) {
            float d2a = (float)(dd*dd);
            if (d2a >= v) break;                     // exact: g >= 0
            float d2b = (float)((dd+1)*(dd+1));
            int jl = jj - dd, jr = jj + dd;
            float ca = (jl >= 0)     ? d2a + grow[jl]   : 3e9f;
            float cb = (jr < WW)     ? d2a + grow[jr]   : 3e9f;
            float cc = (jl - 1 >= 0) ? d2b + grow[jl-1] : 3e9f;
            float cd = (jr + 1 < WW) ? d2b + grow[jr+1] : 3e9f;
            v = fminf(fminf(v, fminf(ca, cb)), fminf(cc, cd));
        }
        gkeys[base0 + s] = (v > 73000.0f) ? SENT_KEY : (int)v;  // exact integer or ~1e9
    }

    // ---- ticket: last split of this mask runs selection
    __threadfence();
    __syncthreads();
    if (tid == 0) {
        int last = (atomicAdd(&d_tick[m], 1) == SPLITS - 1) ? 1 : 0;
        misc[4] = last;
        if (last) d_tick[m] = 0;   // reset for next replay
    }
    __syncthreads();
    if (!misc[4]) return;
    __threadfence();

    // ---- F: selection. p100 = max; p95 = rank ceil(0.95f*n) via coarse+fine smem hists.
    if (n == 0) {
        if (tid == 0) { d_res[m*2] = INFINITY; d_res[m*2+1] = INFINITY; }
    } else {
        int* hist = (int*)(smem + OFF_LIST);     // alias (list dead here)
        int* fine = hist + 288;
        for (int k = tid; k < 544; k += T) hist[k] = 0;
        __syncthreads();
        int locmax = 0;
        for (int s = tid; s < n; s += T) {
            int key = gkeys[s];
            locmax = max(locmax, key);
            int bin = key >> 8;
            unsigned am = __activemask();
            unsigned grp = __match_any_sync(am, bin);
            if ((__ffs(grp) - 1) == lane) atomicAdd(&hist[bin], __popc(grp));
        }
        atomicMax(&misc[1], locmax);
        __syncthreads();
        if (tid == 0) {
            int r95 = (int)ceilf(0.95f * (float)n);   // matches jnp f32 semantics
            r95 = max(1, min(r95, n));
            int cum = 0, cb = 287;
            for (int k = 0; k < 288; k++) {
                if (cum + hist[k] >= r95) { cb = k; break; }
                cum += hist[k];
            }
            misc[2] = cb; misc[3] = r95 - cum;
        }
        __syncthreads();
        int cbv = misc[2];
        for (int s = tid; s < n; s += T) {
            int key = gkeys[s];
            bool hit = ((key >> 8) == cbv);
            unsigned am = __activemask();
            unsigned hm = __ballot_sync(am, hit);
            if (hit) {
                int fb = key & 255;
                unsigned grp = __match_any_sync(hm, fb);
                if ((__ffs(grp) - 1) == lane) atomicAdd(&fine[fb], __popc(grp));
            }
        }
        __syncthreads();
        if (tid == 0) {
            int cum = 0, key95 = cbv << 8;
            for (int k = 0; k < 256; k++) {
                cum += fine[k];
                if (cum >= misc[3]) { key95 += k; break; }
            }
            int keymax = misc[1];
            d_res[m*2+0] = (key95  == SENT_KEY) ? sqrtf(1e9f) : sqrtf((float)key95);
            d_res[m*2+1] = (keymax == SENT_KEY) ? sqrtf(1e9f) : sqrtf((float)keymax);
        }
    }

    // ---- G: final reduce by last mask to finish (order-independent -> deterministic)
    __threadfence();
    __syncthreads();
    if (tid == 0 && atomicAdd(&d_done, 1) == NM - 1) {
        __threadfence();
        float s100 = 0.0f, s95 = 0.0f;
        #pragma unroll
        for (int p = 0; p < NP; p++) {
            s95  += fmaxf(d_res[(2*p)*2 + 0], d_res[(2*p+1)*2 + 0]);
            s100 += fmaxf(d_res[(2*p)*2 + 1], d_res[(2*p+1)*2 + 1]);
        }
        out[0] = s100 / (float)NP;
        out[1] = s95  / (float)NP;
        d_done = 0;   // reset for next replay
    }
}

extern "C" void kernel_launch(void* const* d_in, const int* in_sizes, int n_in,
                              void* d_out, int out_size) {
    const float* logits = (const float*)d_in[0];
    const int*   target = (const int*)d_in[1];
    float* out = (float*)d_out;

    cudaFuncSetAttribute(mega_kernel, cudaFuncAttributeMaxDynamicSharedMemorySize, SMEM_TOTAL);
    argmax_kernel<<<(BB*HW/4 + 255)/256, 256>>>(logits);
    mega_kernel<<<dim3(NM, SPLITS), 1024, SMEM_TOTAL>>>(target, out);
}